// round 2
// baseline (speedup 1.0000x reference)
#include <cuda_runtime.h>
#include <cstdint>

// Problem constants
#define B_ROWS 8192
#define C_ROWS 10000
#define D_DIM  512

// Scratch (no dynamic allocation allowed).
__device__ float g_row_dist[B_ROWS];
__device__ int   g_is64;

// ---------------------------------------------------------------------------
// Kernel 0: detect labels dtype (int32 vs int64).
// Reads the first 2048 int64-interpreted words = 16 KB, which is in-bounds
// whether the buffer is 8192*int32 (32 KB) or 8192*int64 (64 KB).
// If labels are genuine int64 with values in [0, 10000), every 64-bit word is
// < 10000. If the buffer is int32, a 64-bit read packs TWO labels, so the
// value is >= 2^32 whenever the second label != 0 — caught immediately.
// ---------------------------------------------------------------------------
__global__ __launch_bounds__(256)
void detect_label_dtype(const unsigned long long* __restrict__ lw)
{
    const int t = threadIdx.x;
    int bad = 0;
    #pragma unroll
    for (int i = 0; i < 2048 / 256; i++) {
        unsigned long long v = lw[t + i * 256];
        if (v >= (unsigned long long)C_ROWS) bad = 1;
    }
    bad = __syncthreads_or(bad);
    if (t == 0) g_is64 = bad ? 0 : 1;
}

// ---------------------------------------------------------------------------
// Kernel 1: one CTA per sample row. 128 threads x float4 = 512 floats/row.
// Computes clamped squared distance ||x_i - centers[labels_i]||^2.
// ---------------------------------------------------------------------------
__global__ __launch_bounds__(128, 16)
void center_loss_row_kernel(const float* __restrict__ x,
                            const void* __restrict__ labels,
                            const float* __restrict__ centers,
                            float* __restrict__ row_dist)
{
    const int row = blockIdx.x;
    const int t   = threadIdx.x;          // 0..127

    long long lbl;
    if (g_is64)
        lbl = ((const long long*)labels)[row];
    else
        lbl = (long long)((const int*)labels)[row];

    const float4* __restrict__ xr =
        reinterpret_cast<const float4*>(x + (size_t)row * D_DIM);
    const float4* __restrict__ cr =
        reinterpret_cast<const float4*>(centers + (size_t)lbl * D_DIM);

    float4 a = xr[t];
    float4 c = cr[t];

    float dx = a.x - c.x;
    float dy = a.y - c.y;
    float dz = a.z - c.z;
    float dw = a.w - c.w;
    float s = dx * dx + dy * dy + dz * dz + dw * dw;

    // Warp reduce (4 warps of 32)
    #pragma unroll
    for (int off = 16; off > 0; off >>= 1)
        s += __shfl_xor_sync(0xFFFFFFFFu, s, off);

    __shared__ float warp_sums[4];
    const int warp = t >> 5;
    const int lane = t & 31;
    if (lane == 0) warp_sums[warp] = s;
    __syncthreads();

    if (t == 0) {
        float dist = warp_sums[0] + warp_sums[1] + warp_sums[2] + warp_sums[3];
        dist = fminf(fmaxf(dist, 1e-12f), 1e12f);   // clamp [1e-12, 1e12]
        row_dist[row] = dist;
    }
}

// ---------------------------------------------------------------------------
// Kernel 2: deterministic single-CTA reduction of the 8192 row distances,
// writes mean to d_out[0].
// ---------------------------------------------------------------------------
__global__ __launch_bounds__(1024)
void center_loss_reduce_kernel(const float* __restrict__ row_dist,
                               float* __restrict__ out)
{
    const int t = threadIdx.x;            // 0..1023
    float s = 0.0f;
    #pragma unroll
    for (int i = 0; i < B_ROWS / 1024; i++)        // 8 per thread, fixed order
        s += row_dist[t + i * 1024];

    #pragma unroll
    for (int off = 16; off > 0; off >>= 1)
        s += __shfl_xor_sync(0xFFFFFFFFu, s, off);

    __shared__ float warp_sums[32];
    const int warp = t >> 5;
    const int lane = t & 31;
    if (lane == 0) warp_sums[warp] = s;
    __syncthreads();

    if (warp == 0) {
        float v = warp_sums[lane];        // 32 warps -> 32 values
        #pragma unroll
        for (int off = 16; off > 0; off >>= 1)
            v += __shfl_xor_sync(0xFFFFFFFFu, v, off);
        if (lane == 0)
            out[0] = v * (1.0f / (float)B_ROWS);
    }
}

// ---------------------------------------------------------------------------
// Launch. Inputs identified BY SIZE (robust to metadata ordering):
//   x:       8192*512  = 4,194,304 elems (f32)
//   labels:  8192 elems (i32 or i64 — detected on device)
//   centers: 10000*512 = 5,120,000 elems (f32)
// Output: scalar f32.
// ---------------------------------------------------------------------------
extern "C" void kernel_launch(void* const* d_in, const int* in_sizes, int n_in,
                              void* d_out, int out_size)
{
    const float* x       = nullptr;
    const void*  labels  = nullptr;
    const float* centers = nullptr;

    for (int i = 0; i < n_in; i++) {
        if (in_sizes[i] == B_ROWS * D_DIM)       x       = (const float*)d_in[i];
        else if (in_sizes[i] == B_ROWS)          labels  = d_in[i];
        else if (in_sizes[i] == C_ROWS * D_DIM)  centers = (const float*)d_in[i];
    }

    float* out = (float*)d_out;

    float* row_dist;
    cudaGetSymbolAddress((void**)&row_dist, g_row_dist);

    detect_label_dtype<<<1, 256>>>((const unsigned long long*)labels);
    center_loss_row_kernel<<<B_ROWS, 128>>>(x, labels, centers, row_dist);
    center_loss_reduce_kernel<<<1, 1024>>>(row_dist, out);
}

// round 3
// speedup vs baseline: 1.2516x; 1.2516x over previous
#include <cuda_runtime.h>
#include <cstdint>

#define B_ROWS 8192
#define C_ROWS 10000
#define D_DIM  512
#define WARPS_PER_CTA 8
#define GRID_CTAS (B_ROWS / WARPS_PER_CTA)   // 1024

// ---------------------------------------------------------------------------
// Single fused kernel:
//  - per-CTA in-kernel labels-dtype detection (int32 vs int64)
//  - one WARP per sample row: 32 threads x 4 float4 = 512 floats
//  - clamp per row, CTA partial sum, one atomicAdd(out, partial/B) per CTA
// ---------------------------------------------------------------------------
__global__ __launch_bounds__(32 * WARPS_PER_CTA, 8)
void center_loss_fused(const float* __restrict__ x,
                       const void*  __restrict__ labels,
                       const float* __restrict__ centers,
                       float* __restrict__ out)
{
    __shared__ int   s_is64;
    __shared__ float s_part[WARPS_PER_CTA];

    const int t    = threadIdx.x;
    const int warp = t >> 5;
    const int lane = t & 31;

    // --- dtype detect: first 8 u64-interpreted words (64 B, in-bounds for
    // both 8192*i32 and 8192*i64 layouts). Genuine i64 labels < 10000 mean
    // every word < 10000; an i32 buffer packs two labels per word, so any
    // nonzero second label pushes the word >= 2^32. L2-broadcast, ~free.
    if (warp == 0) {
        unsigned long long v =
            ((const unsigned long long*)labels)[lane & 7];
        unsigned big = __ballot_sync(0xFFFFFFFFu, v >= (unsigned long long)C_ROWS);
        if (lane == 0) s_is64 = (big == 0u) ? 1 : 0;
    }
    __syncthreads();
    const int is64 = s_is64;

    // --- one warp per row
    const int row = blockIdx.x * WARPS_PER_CTA + warp;   // 0..8191

    long long lbl;
    if (is64) lbl = ((const long long*)labels)[row];
    else      lbl = (long long)((const int*)labels)[row];

    const float4* __restrict__ xr =
        reinterpret_cast<const float4*>(x + (size_t)row * D_DIM);
    const float4* __restrict__ cr =
        reinterpret_cast<const float4*>(centers + (size_t)lbl * D_DIM);

    // 4 float4 from each row per thread -> MLP=8 outstanding 16B loads
    float4 a0 = xr[lane];        float4 c0 = cr[lane];
    float4 a1 = xr[lane + 32];   float4 c1 = cr[lane + 32];
    float4 a2 = xr[lane + 64];   float4 c2 = cr[lane + 64];
    float4 a3 = xr[lane + 96];   float4 c3 = cr[lane + 96];

    float s = 0.0f;
    {
        float d;
        d = a0.x - c0.x; s = fmaf(d, d, s);
        d = a0.y - c0.y; s = fmaf(d, d, s);
        d = a0.z - c0.z; s = fmaf(d, d, s);
        d = a0.w - c0.w; s = fmaf(d, d, s);
        d = a1.x - c1.x; s = fmaf(d, d, s);
        d = a1.y - c1.y; s = fmaf(d, d, s);
        d = a1.z - c1.z; s = fmaf(d, d, s);
        d = a1.w - c1.w; s = fmaf(d, d, s);
        d = a2.x - c2.x; s = fmaf(d, d, s);
        d = a2.y - c2.y; s = fmaf(d, d, s);
        d = a2.z - c2.z; s = fmaf(d, d, s);
        d = a2.w - c2.w; s = fmaf(d, d, s);
        d = a3.x - c3.x; s = fmaf(d, d, s);
        d = a3.y - c3.y; s = fmaf(d, d, s);
        d = a3.z - c3.z; s = fmaf(d, d, s);
        d = a3.w - c3.w; s = fmaf(d, d, s);
    }

    // warp reduce -> full row distance on lane 0
    #pragma unroll
    for (int off = 16; off > 0; off >>= 1)
        s += __shfl_xor_sync(0xFFFFFFFFu, s, off);

    if (lane == 0) {
        // clamp per row, then pre-scale by 1/B
        float dist = fminf(fmaxf(s, 1e-12f), 1e12f);
        s_part[warp] = dist;
    }
    __syncthreads();

    if (t == 0) {
        float p = 0.0f;
        #pragma unroll
        for (int w = 0; w < WARPS_PER_CTA; w++) p += s_part[w];
        atomicAdd(out, p * (1.0f / (float)B_ROWS));
    }
}

// ---------------------------------------------------------------------------
// Launch. Inputs identified BY SIZE (robust to metadata ordering):
//   x:       8192*512  = 4,194,304 elems (f32)
//   labels:  8192 elems (i32 or i64 — detected on device)
//   centers: 10000*512 = 5,120,000 elems (f32)
// Output: scalar f32 (accumulated via atomics; zeroed each call).
// ---------------------------------------------------------------------------
extern "C" void kernel_launch(void* const* d_in, const int* in_sizes, int n_in,
                              void* d_out, int out_size)
{
    const float* x       = nullptr;
    const void*  labels  = nullptr;
    const float* centers = nullptr;

    for (int i = 0; i < n_in; i++) {
        if (in_sizes[i] == B_ROWS * D_DIM)       x       = (const float*)d_in[i];
        else if (in_sizes[i] == B_ROWS)          labels  = d_in[i];
        else if (in_sizes[i] == C_ROWS * D_DIM)  centers = (const float*)d_in[i];
    }

    float* out = (float*)d_out;

    // Zero the accumulator every call (graph-capturable stream op).
    cudaMemsetAsync(out, 0, sizeof(float));

    center_loss_fused<<<GRID_CTAS, 32 * WARPS_PER_CTA>>>(x, labels, centers, out);
}